// round 10
// baseline (speedup 1.0000x reference)
#include <cuda_runtime.h>

// Haar DWT2: x[8,64,512,512] f32 -> (ll, lh, hl, hh) each [8,64,256,256],
// concatenated into d_out in that order.
//
// Persistent grid-stride version: grid sized to resident capacity so the
// outstanding-load pool never drains on CTA retire/launch. Each work unit is
// 2 output rows x 4 output cols (8 front-batched LDG.128 -> 8 STG.128).

#define IN_W      512
#define OUT_W     256
#define IN_PLANE  (512*512)
#define OUT_PLANE (256*256)
#define SUBBAND   (512*256*256)

#define N_UNITS   (512u * 128u * 64u)   // 4,194,304 work units
#define N_BLOCKS  912                   // 152 SMs * 6 resident CTAs
#define N_THREADS 256

__global__ void __launch_bounds__(N_THREADS, 6) haar_dwt2_kernel(
    const float* __restrict__ x, float* __restrict__ out)
{
    const unsigned stride = N_BLOCKS * N_THREADS;
    unsigned idx = blockIdx.x * N_THREADS + threadIdx.x;

    const float S = 0.5f;

    for (; idx < N_UNITS; idx += stride) {
        unsigned t   = idx & 63u;          // 0..63  -> output cols [4t, 4t+3]
        unsigned op  = (idx >> 6) & 127u;  // 0..127 output row pair
        unsigned bc  = idx >> 13;          // 0..511 plane

        const float* base = x + (size_t)bc * IN_PLANE + (size_t)(4u * op) * IN_W + 8u * t;

        // 8 independent 128-bit streaming loads, front-batched.
        float4 r0a = __ldcs(reinterpret_cast<const float4*>(base));
        float4 r0b = __ldcs(reinterpret_cast<const float4*>(base + 4));
        float4 r1a = __ldcs(reinterpret_cast<const float4*>(base + IN_W));
        float4 r1b = __ldcs(reinterpret_cast<const float4*>(base + IN_W + 4));
        float4 r2a = __ldcs(reinterpret_cast<const float4*>(base + 2*IN_W));
        float4 r2b = __ldcs(reinterpret_cast<const float4*>(base + 2*IN_W + 4));
        float4 r3a = __ldcs(reinterpret_cast<const float4*>(base + 3*IN_W));
        float4 r3b = __ldcs(reinterpret_cast<const float4*>(base + 3*IN_W + 4));

        size_t obase = (size_t)bc * OUT_PLANE + (size_t)(2u * op) * OUT_W + 4u * t;

        // ---- output row 0 (input rows 0,1) ----
        {
            float4 ll, lh, hl, hh;
            {
                float ab = r0a.x + r0a.y, cd = r1a.x + r1a.y;
                float amb = r0a.x - r0a.y, cmd = r1a.x - r1a.y;
                ll.x = (ab + cd) * S; lh.x = (ab - cd) * S;
                hl.x = (amb + cmd) * S; hh.x = (amb - cmd) * S;
            }
            {
                float ab = r0a.z + r0a.w, cd = r1a.z + r1a.w;
                float amb = r0a.z - r0a.w, cmd = r1a.z - r1a.w;
                ll.y = (ab + cd) * S; lh.y = (ab - cd) * S;
                hl.y = (amb + cmd) * S; hh.y = (amb - cmd) * S;
            }
            {
                float ab = r0b.x + r0b.y, cd = r1b.x + r1b.y;
                float amb = r0b.x - r0b.y, cmd = r1b.x - r1b.y;
                ll.z = (ab + cd) * S; lh.z = (ab - cd) * S;
                hl.z = (amb + cmd) * S; hh.z = (amb - cmd) * S;
            }
            {
                float ab = r0b.z + r0b.w, cd = r1b.z + r1b.w;
                float amb = r0b.z - r0b.w, cmd = r1b.z - r1b.w;
                ll.w = (ab + cd) * S; lh.w = (ab - cd) * S;
                hl.w = (amb + cmd) * S; hh.w = (amb - cmd) * S;
            }
            __stcs(reinterpret_cast<float4*>(out + obase), ll);
            __stcs(reinterpret_cast<float4*>(out + obase + (size_t)SUBBAND), lh);
            __stcs(reinterpret_cast<float4*>(out + obase + (size_t)SUBBAND*2), hl);
            __stcs(reinterpret_cast<float4*>(out + obase + (size_t)SUBBAND*3), hh);
        }

        // ---- output row 1 (input rows 2,3) ----
        {
            size_t obase1 = obase + OUT_W;
            float4 ll, lh, hl, hh;
            {
                float ab = r2a.x + r2a.y, cd = r3a.x + r3a.y;
                float amb = r2a.x - r2a.y, cmd = r3a.x - r3a.y;
                ll.x = (ab + cd) * S; lh.x = (ab - cd) * S;
                hl.x = (amb + cmd) * S; hh.x = (amb - cmd) * S;
            }
            {
                float ab = r2a.z + r2a.w, cd = r3a.z + r3a.w;
                float amb = r2a.z - r2a.w, cmd = r3a.z - r3a.w;
                ll.y = (ab + cd) * S; lh.y = (ab - cd) * S;
                hl.y = (amb + cmd) * S; hh.y = (amb - cmd) * S;
            }
            {
                float ab = r2b.x + r2b.y, cd = r3b.x + r3b.y;
                float amb = r2b.x - r2b.y, cmd = r3b.x - r3b.y;
                ll.z = (ab + cd) * S; lh.z = (ab - cd) * S;
                hl.z = (amb + cmd) * S; hh.z = (amb - cmd) * S;
            }
            {
                float ab = r2b.z + r2b.w, cd = r3b.z + r3b.w;
                float amb = r2b.z - r2b.w, cmd = r3b.z - r3b.w;
                ll.w = (ab + cd) * S; lh.w = (ab - cd) * S;
                hl.w = (amb + cmd) * S; hh.w = (amb - cmd) * S;
            }
            __stcs(reinterpret_cast<float4*>(out + obase1), ll);
            __stcs(reinterpret_cast<float4*>(out + obase1 + (size_t)SUBBAND), lh);
            __stcs(reinterpret_cast<float4*>(out + obase1 + (size_t)SUBBAND*2), hl);
            __stcs(reinterpret_cast<float4*>(out + obase1 + (size_t)SUBBAND*3), hh);
        }
    }
}

extern "C" void kernel_launch(void* const* d_in, const int* in_sizes, int n_in,
                              void* d_out, int out_size)
{
    const float* x = (const float*)d_in[0];
    float* out = (float*)d_out;
    haar_dwt2_kernel<<<N_BLOCKS, N_THREADS>>>(x, out);
}